// round 6
// baseline (speedup 1.0000x reference)
#include <cuda_runtime.h>
#include <cuda_bf16.h>

// Problem constants: x,y [4096, 16, 128] f32, out [4096, 99, 128] f32.
#define N_EDGES   4096
#define DIM_IN    16
#define DIM_OUT   99
#define CHANNELS  128
#define VGROUPS   (CHANNELS / 4)   // 32 float4 groups (= warp width)
#define NNZ_CAP   2048
#define MAX_ROW   48               // max CG entries per output row

#define NWARPS    9
#define NTHREADS  (NWARPS * 32)    // 288
#define ROWS_PER_WARP 11           // 9 * 11 = 99

// Compact CSR of the CG metadata, rows sorted by mu1 with reuse flags.
//  entry.x: bit0           = "same mu1 as previous entry" (skip x reload)
//           bits [1..15]   = mu1*512  (byte offset of x float4 row)
//           bits [16..31]  = mu2*512  (byte offset of y float4 row)
//  entry.y: cg bits
__device__ int  g_off[DIM_OUT + 1];
__device__ int2 g_ent[NNZ_CAP];

// Deterministic build: stage COO in shared, count+prefix, then one thread per
// output row collects its entries (original order), stable-sorts by mu1, and
// emits flagged entries. Deterministic => identical output on every call.
__global__ void build_csr_kernel(const int* __restrict__ mu1,
                                 const int* __restrict__ mu2,
                                 const int* __restrict__ mu3,
                                 const float* __restrict__ cg,
                                 int nnz)
{
    __shared__ int   s1[NNZ_CAP];
    __shared__ int   s2[NNZ_CAP];
    __shared__ int   s3[NNZ_CAP];
    __shared__ float sc[NNZ_CAP];
    __shared__ int   s_off[DIM_OUT + 1];

    const int tid = threadIdx.x;
    const int nt  = blockDim.x;

    for (int j = tid; j < nnz; j += nt) {
        s1[j] = mu1[j];
        s2[j] = mu2[j];
        s3[j] = mu3[j];
        sc[j] = cg[j];
    }
    __syncthreads();

    if (tid == 0) {
        int acc = 0;
        s_off[0] = 0;
        // counts + exclusive prefix in one serial pass set below
    }
    __syncthreads();

    // per-row counts into s_off[k+1]
    if (tid < DIM_OUT) {
        int c = 0;
        for (int j = 0; j < nnz; ++j) c += (s3[j] == tid);
        s_off[tid + 1] = c;
    }
    __syncthreads();
    if (tid == 0) {
        s_off[0] = 0;
        for (int k = 0; k < DIM_OUT; ++k) s_off[k + 1] += s_off[k];
    }
    __syncthreads();

    if (tid <= DIM_OUT) g_off[tid] = s_off[tid];

    if (tid < DIM_OUT) {
        const int k    = tid;
        const int base = s_off[k];

        // collect this row's COO indices in original order
        int idx[MAX_ROW];
        int cnt = 0;
        for (int j = 0; j < nnz; ++j) {
            if (s3[j] == k && cnt < MAX_ROW) idx[cnt++] = j;
        }
        // stable insertion sort by mu1 (preserves original order within runs)
        for (int a = 1; a < cnt; ++a) {
            int ja = idx[a];
            int key = s1[ja];
            int b = a - 1;
            while (b >= 0 && s1[idx[b]] > key) { idx[b + 1] = idx[b]; --b; }
            idx[b + 1] = ja;
        }
        // emit with reuse flags
        int prev = -1;
        for (int p = 0; p < cnt; ++p) {
            const int j  = idx[p];
            const int m1 = s1[j];
            const int fl = (m1 == prev) ? 1 : 0;
            prev = m1;
            g_ent[base + p] = make_int2((m1 * 512) | fl | ((s2[j] * 512) << 16),
                                        __float_as_int(sc[j]));
        }
    }
}

// Main kernel: one block per edge, 288 threads = 9 warps.
// Warp w owns rows k = w + 9r (interleaved for balance); lanes = channel groups.
// Metadata read via uniform __ldg broadcast (L1-resident, no smem staging).
__global__ __launch_bounds__(NTHREADS)
void tp_main_kernel(const float4* __restrict__ x,
                    const float4* __restrict__ y,
                    float4* __restrict__ out)
{
    __shared__ float4 xs[DIM_IN * VGROUPS];   // 8 KB
    __shared__ float4 ys[DIM_IN * VGROUPS];   // 8 KB
    __shared__ int    so[DIM_OUT + 1];

    const int n    = blockIdx.x;
    const int tid  = threadIdx.x;
    const int w    = tid >> 5;
    const int lane = tid & 31;

    const float4* xb = x + (size_t)n * (DIM_IN * VGROUPS);
    const float4* yb = y + (size_t)n * (DIM_IN * VGROUPS);
    for (int i = tid; i < DIM_IN * VGROUPS; i += NTHREADS) {
        xs[i] = xb[i];
        ys[i] = yb[i];
    }
    if (tid <= DIM_OUT) so[tid] = g_off[tid];
    __syncthreads();

    const char* xc = (const char*)xs + lane * 16;
    const char* yc = (const char*)ys + lane * 16;

    float4* ob = out + (size_t)n * (DIM_OUT * VGROUPS) + lane;

#pragma unroll
    for (int r = 0; r < ROWS_PER_WARP; ++r) {
        const int k   = w + NWARPS * r;       // uniform per warp
        const int beg = so[k];
        const int end = so[k + 1];

        float4 acc = make_float4(0.f, 0.f, 0.f, 0.f);
        float4 a   = make_float4(0.f, 0.f, 0.f, 0.f);

#pragma unroll 4
        for (int j = beg; j < end; ++j) {
            const int2  e = __ldg(&g_ent[j]); // uniform broadcast, L1-hot
            const float c = __int_as_float(e.y);
            if (!(e.x & 1))                   // warp-uniform: reload x only on new mu1
                a = *(const float4*)(xc + (e.x & 0xfffe));
            const float4 b = *(const float4*)(yc + ((unsigned)e.x >> 16));
            acc.x = fmaf(c * a.x, b.x, acc.x);
            acc.y = fmaf(c * a.y, b.y, acc.y);
            acc.z = fmaf(c * a.z, b.z, acc.z);
            acc.w = fmaf(c * a.w, b.w, acc.w);
        }
        ob[(size_t)k * VGROUPS] = acc;
    }
}

extern "C" void kernel_launch(void* const* d_in, const int* in_sizes, int n_in,
                              void* d_out, int out_size)
{
    const float* x   = (const float*)d_in[0];
    const float* y   = (const float*)d_in[1];
    const int*   mu1 = (const int*)  d_in[2];
    const int*   mu2 = (const int*)  d_in[3];
    const int*   mu3 = (const int*)  d_in[4];
    const float* cg  = (const float*)d_in[5];

    int nnz = in_sizes[5];
    if (nnz > NNZ_CAP) nnz = NNZ_CAP;

    build_csr_kernel<<<1, 1024>>>(mu1, mu2, mu3, cg, nnz);

    tp_main_kernel<<<N_EDGES, NTHREADS>>>((const float4*)x,
                                          (const float4*)y,
                                          (float4*)d_out);
}